// round 6
// baseline (speedup 1.0000x reference)
#include <cuda_runtime.h>
#include <cstdint>

#define TAGS       10
#define SEQ        512
#define BATCHN     8192
#define START_TAG  8
#define STOP_TAG   9
#define NEG_INF    (-10000.0f)

#define STAGES     8
#define EPW        3                  // elements per warp (lanes 0-29)
#define STRIDE     128                // padded stage stride (120 B used)
#define WPB        4                  // warps per block
#define EPB        (EPW * WPB)        // 12 elements per block

// Backpointers: one u64 per (t,b), tag n's argmax nibble at bits 4n. 33.5 MB.
__device__ unsigned long long g_bp[(size_t)SEQ * BATCHN];

__device__ __forceinline__ void cp8(uint32_t s, const void* g) {
    asm volatile("cp.async.ca.shared.global [%0], [%1], 8;\n" :: "r"(s), "l"(g));
}
__device__ __forceinline__ void cp_commit() {
    asm volatile("cp.async.commit_group;\n" ::: "memory");
}
__device__ __forceinline__ void cp_wait6() {
    asm volatile("cp.async.wait_group 6;\n" ::: "memory");
}

// tournament node: value max + first-index argmax (left wins ties; exact compares)
#define TOURN(vl, il, vr, ir, mo, io) \
    { bool _p = (vr) > (vl); mo = _p ? (vr) : (vl); io = _p ? (ir) : (il); }

__global__ __launch_bounds__(128, 1)
void crf_viterbi6(const float* __restrict__ feats,
                  const float* __restrict__ trans,
                  float* __restrict__ out) {
    // warp-private cp.async rings: 4 warps x 8 stages x 128 B = 4 KB
    __shared__ __align__(16) char ring[WPB][STAGES][STRIDE];

    const int tid  = threadIdx.x;
    const int warp = tid >> 5;
    const int lane = tid & 31;
    // lanes 0-29: element e = lane/10, tag j = lane%10. Lanes 30,31 mirror
    // (e=0, j=lane-30): identical compute, never store.
    const int e = (lane < 30) ? (lane / 10) : 0;
    const int j = (lane < 30) ? (lane % 10) : (lane - 30);
    const int gb10 = e * 10;                 // group base lane for all-gather

    const int gw = blockIdx.x * WPB + warp;
    int base_b = gw * EPW;
    if (base_b > BATCHN - EPW) base_b = BATCHN - EPW;   // tail warps duplicate
    const int b = base_b + e;

    // warp slice = 3 elems x 40 B = 120 B contiguous; base is 8-byte aligned
    // for ANY base_b (40 % 8 == 0) -> copy as 15 x cp.async 8B (lanes 0-14).
    const char*  gbase = (const char*)feats + (size_t)base_b * (TAGS * 4);
    const size_t gstep = (size_t)BATCHN * TAGS * 4;     // 327680 B per timestep
    const bool cp_lane = (lane < 15);

    uint32_t s_ring0;
    asm("{ .reg .u64 t; cvta.to.shared.u64 t, %1; cvt.u32.u64 %0, t; }"
        : "=r"(s_ring0) : "l"(&ring[warp][0][0]));

    // transitions: my next-tag row + STOP row
    float T[TAGS], Ts[TAGS];
#pragma unroll
    for (int p = 0; p < TAGS; p++) T[p]  = __ldg(trans + j * TAGS + p);
#pragma unroll
    for (int p = 0; p < TAGS; p++) Ts[p] = __ldg(trans + STOP_TAG * TAGS + p);

    float fv[TAGS];
#pragma unroll
    for (int p = 0; p < TAGS; p++) fv[p] = NEG_INF;
    fv[START_TAG] = 0.0f;

    // prologue: fill stages 0..6 (one commit group per step)
#pragma unroll
    for (int s = 0; s < STAGES - 1; s++) {
        const char* g = gbase + (size_t)s * gstep;
        uint32_t sb = s_ring0 + s * STRIDE;
        if (cp_lane) cp8(sb + lane * 8, g + lane * 8);
        cp_commit();
    }

    const int loff = e * 40 + j * 4;     // conflict-free LDS within a stage
    // backpointer bytes: even tag lanes store (bi_j | bi_{j+1}<<4) into byte
    // j/2 of the u64 record at (t*BATCHN + b). Advance 64 KB per step.
    char* pb = (char*)(g_bp + (size_t)b) + (j >> 1);
    const bool bp_store = (lane < 30) && ((j & 1) == 0);

#pragma unroll 4
    for (int t = 0; t < SEQ; t++) {
        cp_wait6();
        __syncwarp();

        const float f =
            *(const float*)(&ring[warp][t & (STAGES - 1)][0] + loff);

        // prefetch step t+7 into the stage just freed; commit unconditionally
        {
            const int ns = t + STAGES - 1;
            if (ns < SEQ) {
                const char* g = gbase + (size_t)ns * gstep;
                uint32_t sb = s_ring0 + (ns & (STAGES - 1)) * STRIDE;
                if (cp_lane) cp8(sb + lane * 8, g + lane * 8);
            }
            cp_commit();
        }

        // my next-tag: max + first-index argmax over 10 prev tags
        float v0 = fv[0] + T[0], v1 = fv[1] + T[1];
        float v2 = fv[2] + T[2], v3 = fv[3] + T[3];
        float v4 = fv[4] + T[4], v5 = fv[5] + T[5];
        float v6 = fv[6] + T[6], v7 = fv[7] + T[7];
        float v8 = fv[8] + T[8], v9 = fv[9] + T[9];
        float m01, m23, m45, m67, m89, m03, m47, m07, m;
        int   i01, i23, i45, i67, i89, i03, i47, i07, bi;
        TOURN(v0, 0, v1, 1, m01, i01);
        TOURN(v2, 2, v3, 3, m23, i23);
        TOURN(v4, 4, v5, 5, m45, i45);
        TOURN(v6, 6, v7, 7, m67, i67);
        TOURN(v8, 8, v9, 9, m89, i89);
        TOURN(m01, i01, m23, i23, m03, i03);
        TOURN(m45, i45, m67, i67, m47, i47);
        TOURN(m03, i03, m47, i47, m07, i07);
        TOURN(m07, i07, m89, i89, m,   bi);
        const float nf = m + f;

        // all-gather new fv across the 10 tag lanes of my element
#pragma unroll
        for (int p = 0; p < TAGS; p++)
            fv[p] = __shfl_sync(0xffffffffu, nf, gb10 + p);

        // backpointer nibbles: pair with odd neighbor, even lanes store 1 byte
        const int bj = bi | (__shfl_down_sync(0xffffffffu, bi, 1) << 4);
        if (bp_store) *pb = (char)bj;
        pb += (size_t)BATCHN * 8;
    }

    // terminal: max/argmax of fv + trans[STOP] (every lane computes)
    float tv0 = fv[0] + Ts[0], tv1 = fv[1] + Ts[1];
    float tv2 = fv[2] + Ts[2], tv3 = fv[3] + Ts[3];
    float tv4 = fv[4] + Ts[4], tv5 = fv[5] + Ts[5];
    float tv6 = fv[6] + Ts[6], tv7 = fv[7] + Ts[7];
    float tv8 = fv[8] + Ts[8], tv9 = fv[9] + Ts[9];
    float m01, m23, m45, m67, m89, m03, m47, m07, m;
    int   i01, i23, i45, i67, i89, i03, i47, i07, tag;
    TOURN(tv0, 0, tv1, 1, m01, i01);
    TOURN(tv2, 2, tv3, 3, m23, i23);
    TOURN(tv4, 4, tv5, 5, m45, i45);
    TOURN(tv6, 6, tv7, 7, m67, i67);
    TOURN(tv8, 8, tv9, 9, m89, i89);
    TOURN(m01, i01, m23, i23, m03, i03);
    TOURN(m45, i45, m67, i67, m47, i47);
    TOURN(m03, i03, m47, i47, m07, i07);
    TOURN(m07, i07, m89, i89, m,   tag);

    if (j == 0 && lane < 30) {                 // 3 lanes per warp backtrace
        out[b] = m;
        float* __restrict__ path = out + BATCHN;
        const unsigned long long* __restrict__ rec = g_bp + b;
#pragma unroll 16
        for (int t = SEQ - 1; t >= 0; t--) {
            path[(size_t)t * BATCHN + b] = (float)tag;
            const unsigned long long w = rec[(size_t)t * BATCHN];
            tag = (int)((w >> (tag * 4)) & 0xFull);
        }
    }
}

extern "C" void kernel_launch(void* const* d_in, const int* in_sizes, int n_in,
                              void* d_out, int out_size) {
    const float* feats = (const float*)d_in[0];
    const float* trans = (const float*)d_in[1];
    float* out = (float*)d_out;

    // ceil(8192/12) = 683 blocks x 4 warps = 2732 warps (~18 warps/SM)
    crf_viterbi6<<<(BATCHN + EPB - 1) / EPB, 128>>>(feats, trans, out);
}

// round 7
// speedup vs baseline: 1.2149x; 1.2149x over previous
#include <cuda_runtime.h>
#include <cstdint>

#define TAGS       10
#define SEQ        512
#define BATCHN     8192
#define START_TAG  8
#define STOP_TAG   9
#define NEG_INF    (-10000.0f)

#define TBLK       4                        // timesteps per pipeline stage
#define NBLK       (SEQ / TBLK)             // 128 time-blocks
#define STAGES     4
#define EPW        16                       // batch elems per warp
#define TSB        (EPW * TAGS * 4)         // 640 B per warp per timestep
#define WPB        4
#define BPB        (EPW * WPB)              // 64 elems per block

// Backpointers: one u64 per (t,b), tag n's argmax nibble at bits 4n. 33.5 MB.
__device__ unsigned long long g_bp[(size_t)SEQ * BATCHN];

__device__ __forceinline__ void cp16(uint32_t s, const void* g) {
    asm volatile("cp.async.ca.shared.global [%0], [%1], 16;\n" :: "r"(s), "l"(g));
}
__device__ __forceinline__ void cp_commit() {
    asm volatile("cp.async.commit_group;\n" ::: "memory");
}
__device__ __forceinline__ void cp_wait2() {
    asm volatile("cp.async.wait_group 2;\n" ::: "memory");
}

// tournament node: value max + first-index argmax (left wins ties; exact compares)
#define TOURN(vl, il, vr, ir, mo, io) \
    { bool _p = (vr) > (vl); mo = _p ? (vr) : (vl); io = _p ? (ir) : (il); }

__global__ __launch_bounds__(128, 1)
void crf_viterbi7(const float* __restrict__ feats,
                  const float* __restrict__ trans,
                  float* __restrict__ out) {
    // warp-private rings: 4 warps x 4 stages x (4 ts x 640 B) = 40 KB
    __shared__ __align__(16) char ring[WPB][STAGES][TBLK * TSB];

    const int tid   = threadIdx.x;
    const int warp  = tid >> 5;
    const int lane  = tid & 31;
    const int lb    = lane >> 1;        // local elem 0..15
    const int half  = lane & 1;         // 0: next-tags 0..4, 1: next-tags 5..9
    const int nbase = half * 5;
    const int b     = blockIdx.x * BPB + warp * EPW + lb;

    // warp slice base: multiple of 640 B -> 16B-aligned cp16 is safe
    const char*  gbase = (const char*)feats +
                         ((size_t)blockIdx.x * BPB + (size_t)warp * EPW) * (TAGS * 4);
    const size_t gstep = (size_t)BATCHN * TAGS * 4;     // bytes per timestep

    const bool has_c1 = (lane < 8);     // 40 chunks per ts: lane + maybe 32+lane

    uint32_t s_ring0;
    asm("{ .reg .u64 t; cvta.to.shared.u64 t, %1; cvt.u32.u64 %0, t; }"
        : "=r"(s_ring0) : "l"(&ring[warp][0][0]));

    // transitions: my 5 next-tag rows + STOP row
    float T[5][TAGS];
#pragma unroll
    for (int i = 0; i < 5; i++)
#pragma unroll
        for (int p = 0; p < TAGS; p++)
            T[i][p] = __ldg(trans + (nbase + i) * TAGS + p);
    float Ts[TAGS];
#pragma unroll
    for (int p = 0; p < TAGS; p++) Ts[p] = __ldg(trans + STOP_TAG * TAGS + p);

    float fv[TAGS];
#pragma unroll
    for (int p = 0; p < TAGS; p++) fv[p] = NEG_INF;
    fv[START_TAG] = 0.0f;

    // prologue: fill stages 0..2 with time-blocks 0..2 (one commit per block)
#pragma unroll
    for (int s = 0; s < STAGES - 1; s++) {
        uint32_t sb = s_ring0 + s * (TBLK * TSB);
#pragma unroll
        for (int k = 0; k < TBLK; k++) {
            const char* g = gbase + (size_t)(s * TBLK + k) * gstep;
            cp16(sb + k * TSB + lane * 16, g + lane * 16);
            if (has_c1) cp16(sb + k * TSB + (32 + lane) * 16, g + (32 + lane) * 16);
        }
        cp_commit();
    }

    // per-thread smem read offsets within one timestep's 640B slab
    const int offA = lb * 40 + (half ? 24 : 0);
    const int offB = lb * 40 + (half ? 32 : 8);
    const int offS = lb * 40 + (half ? 20 : 16);

    unsigned long long* __restrict__ bp_col = g_bp + b;

    for (int ib = 0; ib < NBLK; ib++) {
        cp_wait2();          // time-block ib's stage is complete
        __syncwarp();

        const char* sp = ring[warp][ib & (STAGES - 1)];

        // prefetch time-block ib+3 into the stage just freed; always commit
        {
            const int nb = ib + STAGES - 1;
            if (nb < NBLK) {
                uint32_t sb = s_ring0 + (nb & (STAGES - 1)) * (TBLK * TSB);
#pragma unroll
                for (int k = 0; k < TBLK; k++) {
                    const char* g = gbase + (size_t)(nb * TBLK + k) * gstep;
                    cp16(sb + k * TSB + lane * 16, g + lane * 16);
                    if (has_c1)
                        cp16(sb + k * TSB + (32 + lane) * 16, g + (32 + lane) * 16);
                }
            }
            cp_commit();
        }

        // ---- 4 timesteps, no fences between them ----
#pragma unroll
        for (int k = 0; k < TBLK; k++) {
            const int t = ib * TBLK + k;
            const char* sk = sp + k * TSB;
            float2 A = *(const float2*)(sk + offA);
            float2 B = *(const float2*)(sk + offB);
            float  s = *(const float*)(sk + offS);
            float f[5];
            if (half) { f[0] = s;   f[1] = A.x; f[2] = A.y; f[3] = B.x; f[4] = B.y; }
            else      { f[0] = A.x; f[1] = A.y; f[2] = B.x; f[3] = B.y; f[4] = s;   }

            float nf[5];
            unsigned bits = 0u;
#pragma unroll
            for (int i = 0; i < 5; i++) {
                float v0 = fv[0] + T[i][0], v1 = fv[1] + T[i][1];
                float v2 = fv[2] + T[i][2], v3 = fv[3] + T[i][3];
                float v4 = fv[4] + T[i][4], v5 = fv[5] + T[i][5];
                float v6 = fv[6] + T[i][6], v7 = fv[7] + T[i][7];
                float v8 = fv[8] + T[i][8], v9 = fv[9] + T[i][9];
                float m01, m23, m45, m67, m89, m03, m47, m07, m;
                int   i01, i23, i45, i67, i89, i03, i47, i07, bi;
                TOURN(v0, 0, v1, 1, m01, i01);
                TOURN(v2, 2, v3, 3, m23, i23);
                TOURN(v4, 4, v5, 5, m45, i45);
                TOURN(v6, 6, v7, 7, m67, i67);
                TOURN(v8, 8, v9, 9, m89, i89);
                TOURN(m01, i01, m23, i23, m03, i03);
                TOURN(m45, i45, m67, i67, m47, i47);
                TOURN(m03, i03, m47, i47, m07, i07);
                TOURN(m07, i07, m89, i89, m,   bi);
                nf[i] = m + f[i];
                bits |= (unsigned)bi << (4 * i);
            }

            // lane-pair exchange of the other half's new fv
#pragma unroll
            for (int i = 0; i < 5; i++) {
                float o = __shfl_xor_sync(0xffffffffu, nf[i], 1);
                fv[i]     = half ? o     : nf[i];
                fv[i + 5] = half ? nf[i] : o;
            }
            unsigned obits = __shfl_xor_sync(0xffffffffu, bits, 1);
            if (!half) {
                unsigned long long w =
                    (unsigned long long)bits | ((unsigned long long)obits << 20);
                bp_col[(size_t)t * BATCHN] = w;
            }
        }
    }

    // terminal: max/argmax of fv + trans[STOP]
    float tv[TAGS];
#pragma unroll
    for (int p = 0; p < TAGS; p++) tv[p] = fv[p] + Ts[p];
    float m01, m23, m45, m67, m89, m03, m47, m07, m;
    int   i01, i23, i45, i67, i89, i03, i47, i07, tag;
    TOURN(tv[0], 0, tv[1], 1, m01, i01);
    TOURN(tv[2], 2, tv[3], 3, m23, i23);
    TOURN(tv[4], 4, tv[5], 5, m45, i45);
    TOURN(tv[6], 6, tv[7], 7, m67, i67);
    TOURN(tv[8], 8, tv[9], 9, m89, i89);
    TOURN(m01, i01, m23, i23, m03, i03);
    TOURN(m45, i45, m67, i67, m47, i47);
    TOURN(m03, i03, m47, i47, m07, i07);
    TOURN(m07, i07, m89, i89, m,   tag);

    if (!half) {
        out[b] = m;
        float* __restrict__ path = out + BATCHN;
#pragma unroll 16
        for (int t = SEQ - 1; t >= 0; t--) {
            path[(size_t)t * BATCHN + b] = (float)tag;
            const unsigned long long w = bp_col[(size_t)t * BATCHN];
            tag = (int)((w >> (tag * 4)) & 0xFull);
        }
    }
}

extern "C" void kernel_launch(void* const* d_in, const int* in_sizes, int n_in,
                              void* d_out, int out_size) {
    const float* feats = (const float*)d_in[0];
    const float* trans = (const float*)d_in[1];
    float* out = (float*)d_out;

    crf_viterbi7<<<BATCHN / BPB, 128>>>(feats, trans, out);   // 128 blocks
}

// round 8
// speedup vs baseline: 1.2410x; 1.0215x over previous
#include <cuda_runtime.h>
#include <cstdint>

#define TAGS       10
#define SEQ        512
#define BATCHN     8192
#define START_TAG  8
#define STOP_TAG   9
#define NEG_INF    (-10000.0f)

#define TBLK       4                        // timesteps per pipeline stage
#define NBLK       (SEQ / TBLK)             // 128 time-blocks
#define STAGES     4
#define EPW        16                       // batch elems per warp
#define TSB        (EPW * TAGS * 4)         // 640 B per warp per timestep
#define WPB        4
#define BPB        (EPW * WPB)              // 64 elems per block

// Backpointers: one u64 per (t,b). LOW u32 = nibbles of tags 0-4 (bit 4i),
// HIGH u32 = nibbles of tags 5-9 (bit 4i). 33.5 MB scratch.
__device__ unsigned long long g_bp[(size_t)SEQ * BATCHN];

__device__ __forceinline__ void cp16(uint32_t s, const void* g) {
    asm volatile("cp.async.ca.shared.global [%0], [%1], 16;\n" :: "r"(s), "l"(g));
}
__device__ __forceinline__ void cp_commit() {
    asm volatile("cp.async.commit_group;\n" ::: "memory");
}
__device__ __forceinline__ void cp_wait2() {
    asm volatile("cp.async.wait_group 2;\n" ::: "memory");
}

// tournament node: value max + first-index argmax (left wins ties; exact compares)
#define TOURN(vl, il, vr, ir, mo, io) \
    { bool _p = (vr) > (vl); mo = _p ? (vr) : (vl); io = _p ? (ir) : (il); }

__global__ __launch_bounds__(128, 1)
void crf_viterbi8(const float* __restrict__ feats,
                  const float* __restrict__ trans,
                  float* __restrict__ out) {
    // warp-private rings: 4 warps x 4 stages x (4 ts x 640 B) = 40 KB
    __shared__ __align__(16) char ring[WPB][STAGES][TBLK * TSB];

    const int tid   = threadIdx.x;
    const int warp  = tid >> 5;
    const int lane  = tid & 31;
    const int lb    = lane >> 1;        // local elem 0..15
    const int half  = lane & 1;         // 0: next-tags 0..4, 1: next-tags 5..9
    const int nbase = half * 5;
    const int b     = blockIdx.x * BPB + warp * EPW + lb;

    const char*  gbase = (const char*)feats +
                         ((size_t)blockIdx.x * BPB + (size_t)warp * EPW) * (TAGS * 4);
    const size_t gstep = (size_t)BATCHN * TAGS * 4;

    const bool has_c1 = (lane < 8);

    uint32_t s_ring0;
    asm("{ .reg .u64 t; cvta.to.shared.u64 t, %1; cvt.u32.u64 %0, t; }"
        : "=r"(s_ring0) : "l"(&ring[warp][0][0]));

    // transitions: my 5 next-tag rows + STOP row
    float T[5][TAGS];
#pragma unroll
    for (int i = 0; i < 5; i++)
#pragma unroll
        for (int p = 0; p < TAGS; p++)
            T[i][p] = __ldg(trans + (nbase + i) * TAGS + p);
    float Ts[TAGS];
#pragma unroll
    for (int p = 0; p < TAGS; p++) Ts[p] = __ldg(trans + STOP_TAG * TAGS + p);

    float fv[TAGS];
#pragma unroll
    for (int p = 0; p < TAGS; p++) fv[p] = NEG_INF;
    fv[START_TAG] = 0.0f;

    // prologue: fill stages 0..2 (one commit group per time-block)
#pragma unroll
    for (int s = 0; s < STAGES - 1; s++) {
        uint32_t sb = s_ring0 + s * (TBLK * TSB);
#pragma unroll
        for (int k = 0; k < TBLK; k++) {
            const char* g = gbase + (size_t)(s * TBLK + k) * gstep;
            cp16(sb + k * TSB + lane * 16, g + lane * 16);
            if (has_c1) cp16(sb + k * TSB + (32 + lane) * 16, g + (32 + lane) * 16);
        }
        cp_commit();
    }

    const int offA = lb * 40 + (half ? 24 : 0);
    const int offB = lb * 40 + (half ? 32 : 8);
    const int offS = lb * 40 + (half ? 20 : 16);

    unsigned* __restrict__ bp32 = (unsigned*)g_bp;

    for (int ib = 0; ib < NBLK; ib++) {
        cp_wait2();
        __syncwarp();

        const char* sp = ring[warp][ib & (STAGES - 1)];

        // prefetch time-block ib+3 into the freed stage; always commit
        {
            const int nb = ib + STAGES - 1;
            if (nb < NBLK) {
                uint32_t sb = s_ring0 + (nb & (STAGES - 1)) * (TBLK * TSB);
#pragma unroll
                for (int k = 0; k < TBLK; k++) {
                    const char* g = gbase + (size_t)(nb * TBLK + k) * gstep;
                    cp16(sb + k * TSB + lane * 16, g + lane * 16);
                    if (has_c1)
                        cp16(sb + k * TSB + (32 + lane) * 16, g + (32 + lane) * 16);
                }
            }
            cp_commit();
        }

        // hoist ALL feat LDS for this time-block (12 LDS, latencies overlap)
        float fb[TBLK][5];
#pragma unroll
        for (int k = 0; k < TBLK; k++) {
            const char* sk = sp + k * TSB;
            float2 A = *(const float2*)(sk + offA);
            float2 B = *(const float2*)(sk + offB);
            float  s = *(const float*)(sk + offS);
            if (half) { fb[k][0] = s;   fb[k][1] = A.x; fb[k][2] = A.y;
                        fb[k][3] = B.x; fb[k][4] = B.y; }
            else      { fb[k][0] = A.x; fb[k][1] = A.y; fb[k][2] = B.x;
                        fb[k][3] = B.y; fb[k][4] = s;   }
        }

        // ---- 4 timesteps, breadth-first tournaments (5 chains interleaved) ----
#pragma unroll
        for (int k = 0; k < TBLK; k++) {
            const int t = ib * TBLK + k;

            float v[5][TAGS];
#pragma unroll
            for (int i = 0; i < 5; i++)
#pragma unroll
                for (int p = 0; p < TAGS; p++)
                    v[i][p] = fv[p] + T[i][p];

            float m1[5][5]; int x1[5][5];
#pragma unroll
            for (int i = 0; i < 5; i++)
#pragma unroll
                for (int q = 0; q < 5; q++)
                    TOURN(v[i][2 * q], 2 * q, v[i][2 * q + 1], 2 * q + 1,
                          m1[i][q], x1[i][q]);

            float m2[5][2]; int x2[5][2];
#pragma unroll
            for (int i = 0; i < 5; i++) {
                TOURN(m1[i][0], x1[i][0], m1[i][1], x1[i][1], m2[i][0], x2[i][0]);
                TOURN(m1[i][2], x1[i][2], m1[i][3], x1[i][3], m2[i][1], x2[i][1]);
            }

            float m3[5]; int x3[5];
#pragma unroll
            for (int i = 0; i < 5; i++)
                TOURN(m2[i][0], x2[i][0], m2[i][1], x2[i][1], m3[i], x3[i]);

            float m4[5]; int x4[5];
#pragma unroll
            for (int i = 0; i < 5; i++)
                TOURN(m3[i], x3[i], m1[i][4], x1[i][4], m4[i], x4[i]);

            float nf[5];
#pragma unroll
            for (int i = 0; i < 5; i++) nf[i] = m4[i] + fb[k][i];

            // lane-pair exchange of the other half's new fv (5 SHFL)
#pragma unroll
            for (int i = 0; i < 5; i++) {
                float o = __shfl_xor_sync(0xffffffffu, nf[i], 1);
                fv[i]     = half ? o     : nf[i];
                fv[i + 5] = half ? nf[i] : o;
            }

            // each lane stores its own 5 nibbles (coalesced 128B STG.32 per warp)
            unsigned bits = (unsigned)x4[0]        | ((unsigned)x4[1] << 4)  |
                            ((unsigned)x4[2] << 8) | ((unsigned)x4[3] << 12) |
                            ((unsigned)x4[4] << 16);
            bp32[2 * ((size_t)t * BATCHN + b) + half] = bits;
        }
    }

    // terminal: max/argmax of fv + trans[STOP]
    float tv[TAGS];
#pragma unroll
    for (int p = 0; p < TAGS; p++) tv[p] = fv[p] + Ts[p];
    float m01, m23, m45, m67, m89, m03, m47, m07, m;
    int   i01, i23, i45, i67, i89, i03, i47, i07, tag;
    TOURN(tv[0], 0, tv[1], 1, m01, i01);
    TOURN(tv[2], 2, tv[3], 3, m23, i23);
    TOURN(tv[4], 4, tv[5], 5, m45, i45);
    TOURN(tv[6], 6, tv[7], 7, m67, i67);
    TOURN(tv[8], 8, tv[9], 9, m89, i89);
    TOURN(m01, i01, m23, i23, m03, i03);
    TOURN(m45, i45, m67, i67, m47, i47);
    TOURN(m03, i03, m47, i47, m07, i07);
    TOURN(m07, i07, m89, i89, m,   tag);

    if (!half) {
        out[b] = m;
        float* __restrict__ path = out + BATCHN;
        const unsigned long long* __restrict__ rec = g_bp + b;
#pragma unroll 16
        for (int t = SEQ - 1; t >= 0; t--) {
            path[(size_t)t * BATCHN + b] = (float)tag;
            const unsigned long long w = rec[(size_t)t * BATCHN];
            const int sh = 4 * tag + ((tag >= 5) ? 12 : 0);
            tag = (int)((w >> sh) & 0xFull);
        }
    }
}

extern "C" void kernel_launch(void* const* d_in, const int* in_sizes, int n_in,
                              void* d_out, int out_size) {
    const float* feats = (const float*)d_in[0];
    const float* trans = (const float*)d_in[1];
    float* out = (float*)d_out;

    crf_viterbi8<<<BATCHN / BPB, 128>>>(feats, trans, out);   // 128 blocks
}